// round 9
// baseline (speedup 1.0000x reference)
#include <cuda_runtime.h>
#include <cuda_fp16.h>
#include <math.h>
#include <stdint.h>

#define NT 4096      // tokens = B*S
#define ND 1024      // hidden
#define NH 512       // intermediate
#define NE 8         // experts

// ---- device scratch (static; no allocations allowed) ----
__device__ int    g_cnt[NE];
__device__ int    g_tokslot[NE * NT];
__device__ float  g_gate[NE * NT];
__device__ __half g_x16[(size_t)NT * ND];
__device__ __half g_win16[(size_t)NE * 2 * NH * ND];
__device__ __half g_wout16[(size_t)NE * ND * NH];
__device__ __half g_h16[(size_t)NE * NT * NH];
__device__ float  g_y[(size_t)NT * 2 * ND];
__device__ float  g_logits_scratch[(size_t)NT * NE];

// ======================= helpers =======================
__device__ __forceinline__ uint32_t smem_u32(const void* p) {
    uint32_t a;
    asm("{ .reg .u64 t; cvta.to.shared.u64 t, %1; cvt.u32.u64 %0, t; }" : "=r"(a) : "l"(p));
    return a;
}
#define CPA16(dst, src) asm volatile("cp.async.cg.shared.global [%0], [%1], 16;" :: "r"(dst), "l"(src))
#define CPCOMMIT()      asm volatile("cp.async.commit_group;")
#define CPWAIT(n)       asm volatile("cp.async.wait_group %0;" :: "n"(n))
#define LDM_X4(r0, r1, r2, r3, addr) \
    asm volatile("ldmatrix.sync.aligned.m8n8.x4.shared.b16 {%0,%1,%2,%3}, [%4];" \
        : "=r"(r0), "=r"(r1), "=r"(r2), "=r"(r3) : "r"(addr))
#define MMA16(d, a, b0, b1) \
    asm volatile("mma.sync.aligned.m16n8k16.row.col.f32.f16.f16.f32 " \
        "{%0,%1,%2,%3}, {%4,%5,%6,%7}, {%8,%9}, {%0,%1,%2,%3};" \
        : "+f"((d)[0]), "+f"((d)[1]), "+f"((d)[2]), "+f"((d)[3]) \
        : "r"((a)[0]), "r"((a)[1]), "r"((a)[2]), "r"((a)[3]), "r"(b0), "r"(b1))

// =====================================================================
__global__ void init_kernel() {
    if (threadIdx.x < NE) g_cnt[threadIdx.x] = 0;
}

// One block per token: logits (8 warp-dots), top-2 softmax dispatch,
// AND fp16 conversion of this token's x row (row is L1-hot).
__global__ void router_kernel(const float* __restrict__ x,
                              const float* __restrict__ wr,
                              float* __restrict__ logits_out,
                              __half* __restrict__ x16) {
    int t = blockIdx.x;
    int w = threadIdx.x >> 5;
    int l = threadIdx.x & 31;
    const float* xr = x + (size_t)t * ND;
    const float* wrow = wr + w * ND;
    float s = 0.f;
    #pragma unroll 8
    for (int j = l; j < ND; j += 32) s += xr[j] * wrow[j];
    #pragma unroll
    for (int o = 16; o > 0; o >>= 1) s += __shfl_xor_sync(0xffffffffu, s, o);
    __shared__ float lg[NE];
    if (l == 0) { lg[w] = s; logits_out[(size_t)t * NE + w] = s; }

    {
        int j = threadIdx.x * 4;
        float4 v = *reinterpret_cast<const float4*>(xr + j);
        __half2* dst = reinterpret_cast<__half2*>(x16 + (size_t)t * ND + j);
        dst[0] = __floats2half2_rn(v.x, v.y);
        dst[1] = __floats2half2_rn(v.z, v.w);
    }

    __syncthreads();
    if (threadIdx.x == 0) {
        int i0 = 0; float v0 = lg[0];
        #pragma unroll
        for (int e = 1; e < NE; ++e) if (lg[e] > v0) { v0 = lg[e]; i0 = e; }
        int i1 = -1; float v1 = -INFINITY;
        #pragma unroll
        for (int e = 0; e < NE; ++e) if (e != i0 && lg[e] > v1) { v1 = lg[e]; i1 = e; }
        float e1 = expf(v1 - v0);
        float inv = 1.f / (1.f + e1);
        int p0 = atomicAdd(&g_cnt[i0], 1);
        g_tokslot[i0 * NT + p0] = t * 2;
        g_gate[i0 * NT + p0]    = inv;
        int p1 = atomicAdd(&g_cnt[i1], 1);
        g_tokslot[i1 * NT + p1] = t * 2 + 1;
        g_gate[i1 * NT + p1]    = e1 * inv;
    }
}

// Merged fp32->fp16 weight convert, grid-stride (w_in then w_out).
#define NWI (NE * 2 * NH * ND / 4)
#define NWO (NE * ND * NH / 4)
__global__ void cvtw_kernel(const float* __restrict__ win, __half* __restrict__ dwin,
                            const float* __restrict__ wout, __half* __restrict__ dwout) {
    int stride = gridDim.x * blockDim.x;
    for (int i = blockIdx.x * blockDim.x + threadIdx.x; i < NWI + NWO; i += stride) {
        const float* s; __half* d; int j;
        if (i < NWI) { s = win; d = dwin; j = i; }
        else         { s = wout; d = dwout; j = i - NWI; }
        float4 v = reinterpret_cast<const float4*>(s)[j];
        reinterpret_cast<__half2*>(d)[2 * j]     = __floats2half2_rn(v.x, v.y);
        reinterpret_cast<__half2*>(d)[2 * j + 1] = __floats2half2_rn(v.z, v.w);
    }
}

// Shared-mem geometry: row = 64B (32 halfs), chunk = 16B, swizzle c^=((row>>1)&3).
// Stage = A(128x32h, 8KB) + B(128x32h, 8KB) = 16KB; 6 stages = 96KB (dynamic).
// Two stages consumed per __syncthreads (sync cadence halved vs 3-stage version).
#define STAGE_BYTES 16384
#define NSTAGE 6
#define SMEM_BYTES (NSTAGE * STAGE_BYTES)

// prefetch one 32-K stage into buffer at smem offset stoff (elements offset koff)
#define PF(stoff, koff) do { \
    uint32_t st_ = sb + (stoff); \
    CPA16(st_ + dA0, asrc0 + (koff)); \
    CPA16(st_ + dA1, asrc1 + (koff)); \
    CPA16(st_ + 8192 + dA0, bsrc0 + (koff)); \
    CPA16(st_ + 8192 + dA1, bsrc1 + (koff)); \
    CPCOMMIT(); } while (0)

// =====================================================================
// ffn1: C[128 x 128] = A(gathered x16 rows) @ B^T, fp16 mma, K = 1024.
// B tile rows interleaved per-warp (a/b halves pair thread-locally).
// Epilogue: h = silu(a)*b -> g_h16, all-register.
// =====================================================================
__global__ void __launch_bounds__(256, 2)
ffn1_h(void) {
    extern __shared__ __align__(128) uint8_t smem[];
    int e = blockIdx.z;
    int cnt = g_cnt[e];
    int m0 = blockIdx.y * 128;
    if (m0 >= cnt) return;
    int n0 = blockIdx.x * 64;

    uint32_t sb = smem_u32(smem);
    int t = threadIdx.x;
    int lane = t & 31, wid = t >> 5;
    int wm = wid & 1, wn = wid >> 1;          // warp grid 2(M) x 4(N)
    int grp = lane >> 2, tig = lane & 3;
    int rA = (lane & 7) + ((lane >> 3) & 1) * 8;   // ldmatrix row-in-16
    int csel = lane >> 4;                          // ldmatrix chunk select

    int lr = t >> 2;             // 0..63
    int lc = t & 3;
    int r0 = m0 + lr, r1 = r0 + 64;
    int rc0 = r0 < cnt ? r0 : cnt - 1;
    int rc1 = r1 < cnt ? r1 : cnt - 1;
    const __half* asrc0 = g_x16 + (size_t)(g_tokslot[e * NT + rc0] >> 1) * ND + lc * 8;
    const __half* asrc1 = g_x16 + (size_t)(g_tokslot[e * NT + rc1] >> 1) * ND + lc * 8;
    // interleaved B-row mapping for tile rows nn0=lr, nn1=lr+64
    int nn0 = lr, nn1 = lr + 64;
    int j0 = nn0 & 31, j1 = nn1 & 31;
    int brow0 = (j0 < 16) ? (n0 + (nn0 >> 5) * 16 + j0) : (NH + n0 + (nn0 >> 5) * 16 + j0 - 16);
    int brow1 = (j1 < 16) ? (n0 + (nn1 >> 5) * 16 + j1) : (NH + n0 + (nn1 >> 5) * 16 + j1 - 16);
    const __half* bsrc0 = g_win16 + ((size_t)e * (2 * NH) + brow0) * ND + lc * 8;
    const __half* bsrc1 = g_win16 + ((size_t)e * (2 * NH) + brow1) * ND + lc * 8;
    uint32_t swc = (uint32_t)((lc ^ ((lr >> 1) & 3)) << 4);
    uint32_t dA0 = lr * 64 + swc;
    uint32_t dA1 = dA0 + 4096;

    float acc[4][4][4];
    #pragma unroll
    for (int i = 0; i < 4; ++i)
        #pragma unroll
        for (int j = 0; j < 4; ++j)
            #pragma unroll
            for (int q = 0; q < 4; ++q) acc[i][j][q] = 0.f;

    #pragma unroll
    for (int s = 0; s < 4; ++s) PF(s * STAGE_BYTES, s * 32);

    const int NK = ND / 32;   // 32
    int b0 = 0;               // buffer index of stage kt
    for (int kt = 0; kt < NK; kt += 2) {
        if (kt + 2 < NK) { CPWAIT(2); } else { CPWAIT(0); }
        __syncthreads();
        if (kt + 4 < NK) {
            int p4 = b0 + 4; if (p4 >= NSTAGE) p4 -= NSTAGE;
            PF(p4 * STAGE_BYTES, (kt + 4) * 32);
            if (kt + 5 < NK) {
                int p5 = p4 + 1; if (p5 >= NSTAGE) p5 -= NSTAGE;
                PF(p5 * STAGE_BYTES, (kt + 5) * 32);
            }
        }
        int b1 = b0 + 1; if (b1 >= NSTAGE) b1 -= NSTAGE;
        #pragma unroll
        for (int half = 0; half < 2; ++half) {
            uint32_t As = sb + (half ? b1 : b0) * STAGE_BYTES;
            uint32_t Bs = As + 8192;
            #pragma unroll
            for (int ks = 0; ks < 2; ++ks) {
                uint32_t a[4][4], B0[4], B1[4];
                int ch = ks * 2 + csel;
                #pragma unroll
                for (int mt = 0; mt < 4; ++mt) {
                    int row = wm * 64 + mt * 16 + rA;
                    uint32_t ad = As + row * 64 + ((ch ^ ((row >> 1) & 3)) << 4);
                    LDM_X4(a[mt][0], a[mt][1], a[mt][2], a[mt][3], ad);
                }
                {
                    int row = wn * 32 + rA;
                    uint32_t bd = Bs + row * 64 + ((ch ^ ((row >> 1) & 3)) << 4);
                    LDM_X4(B0[0], B0[1], B0[2], B0[3], bd);
                    row += 16;
                    bd = Bs + row * 64 + ((ch ^ ((row >> 1) & 3)) << 4);
                    LDM_X4(B1[0], B1[1], B1[2], B1[3], bd);
                }
                #pragma unroll
                for (int mt = 0; mt < 4; ++mt) {
                    MMA16(acc[mt][0], a[mt], B0[0], B0[2]);
                    MMA16(acc[mt][1], a[mt], B0[1], B0[3]);
                    MMA16(acc[mt][2], a[mt], B1[0], B1[2]);
                    MMA16(acc[mt][3], a[mt], B1[1], B1[3]);
                }
            }
        }
        b0 += 2; if (b0 >= NSTAGE) b0 -= NSTAGE;
    }

    // epilogue: acc[mt][nt] (a-cols) pairs with acc[mt][nt+2] (b-cols), nt in {0,1}.
    #pragma unroll
    for (int mt = 0; mt < 4; ++mt) {
        #pragma unroll
        for (int hf = 0; hf < 2; ++hf) {
            int row = wm * 64 + mt * 16 + grp + hf * 8;
            int rr = m0 + row;
            if (rr < cnt) {
                __half* dst = g_h16 + ((size_t)e * NT + rr) * NH + n0 + wn * 16;
                #pragma unroll
                for (int nt = 0; nt < 2; ++nt) {
                    float a0 = acc[mt][nt][hf * 2 + 0];
                    float a1 = acc[mt][nt][hf * 2 + 1];
                    float b0f = acc[mt][nt + 2][hf * 2 + 0];
                    float b1f = acc[mt][nt + 2][hf * 2 + 1];
                    float h0 = a0 / (1.f + __expf(-a0)) * b0f;
                    float h1 = a1 / (1.f + __expf(-a1)) * b1f;
                    *(__half2*)(dst + nt * 8 + 2 * tig) = __floats2half2_rn(h0, h1);
                }
            }
        }
    }
}

// =====================================================================
// ffn2: C[128 x 128] = g_h16 rows @ w_out16 rows^T, K = 512.
// Epilogue: gate-scale, scatter rows to g_y[tokslot].
// =====================================================================
__global__ void __launch_bounds__(256, 2)
ffn2_h(void) {
    extern __shared__ __align__(128) uint8_t smem[];
    int e = blockIdx.z;
    int cnt = g_cnt[e];
    int m0 = blockIdx.y * 128;
    if (m0 >= cnt) return;
    int n0 = blockIdx.x * 128;

    uint32_t sb = smem_u32(smem);
    int t = threadIdx.x;
    int lane = t & 31, wid = t >> 5;
    int wm = wid & 1, wn = wid >> 1;
    int grp = lane >> 2, tig = lane & 3;
    int rA = (lane & 7) + ((lane >> 3) & 1) * 8;
    int csel = lane >> 4;

    int lr = t >> 2;
    int lc = t & 3;
    int r0 = m0 + lr, r1 = r0 + 64;
    int rc0 = r0 < cnt ? r0 : cnt - 1;
    int rc1 = r1 < cnt ? r1 : cnt - 1;
    const __half* asrc0 = g_h16 + ((size_t)e * NT + rc0) * NH + lc * 8;
    const __half* asrc1 = g_h16 + ((size_t)e * NT + rc1) * NH + lc * 8;
    const __half* bsrc0 = g_wout16 + ((size_t)e * ND + n0 + lr) * NH + lc * 8;
    const __half* bsrc1 = g_wout16 + ((size_t)e * ND + n0 + lr + 64) * NH + lc * 8;
    uint32_t swc = (uint32_t)((lc ^ ((lr >> 1) & 3)) << 4);
    uint32_t dA0 = lr * 64 + swc;
    uint32_t dA1 = dA0 + 4096;

    float acc[4][4][4];
    #pragma unroll
    for (int i = 0; i < 4; ++i)
        #pragma unroll
        for (int j = 0; j < 4; ++j)
            #pragma unroll
            for (int q = 0; q < 4; ++q) acc[i][j][q] = 0.f;

    #pragma unroll
    for (int s = 0; s < 4; ++s) PF(s * STAGE_BYTES, s * 32);

    const int NK = NH / 32;   // 16
    int b0 = 0;
    for (int kt = 0; kt < NK; kt += 2) {
        if (kt + 2 < NK) { CPWAIT(2); } else { CPWAIT(0); }
        __syncthreads();
        if (kt + 4 < NK) {
            int p4 = b0 + 4; if (p4 >= NSTAGE) p4 -= NSTAGE;
            PF(p4 * STAGE_BYTES, (kt + 4) * 32);
            if (kt + 5 < NK) {
                int p5 = p4 + 1; if (p5 >= NSTAGE) p5 -= NSTAGE;
                PF(p5 * STAGE_BYTES, (kt + 5) * 32);
            }
        }
        int b1 = b0 + 1; if (b1 >= NSTAGE) b1 -= NSTAGE;
        #pragma unroll
        for (int half = 0; half < 2; ++half) {
            uint32_t As = sb + (half ? b1 : b0) * STAGE_BYTES;
            uint32_t Bs = As + 8192;
            #pragma unroll
            for (int ks = 0; ks < 2; ++ks) {
                uint32_t a[4][4], B0[4], B1[4];
                int ch = ks * 2 + csel;
                #pragma unroll
                for (int mt = 0; mt < 4; ++mt) {
                    int row = wm * 64 + mt * 16 + rA;
                    uint32_t ad = As + row * 64 + ((ch ^ ((row >> 1) & 3)) << 4);
                    LDM_X4(a[mt][0], a[mt][1], a[mt][2], a[mt][3], ad);
                }
                {
                    int row = wn * 32 + rA;
                    uint32_t bd = Bs + row * 64 + ((ch ^ ((row >> 1) & 3)) << 4);
                    LDM_X4(B0[0], B0[1], B0[2], B0[3], bd);
                    row += 16;
                    bd = Bs + row * 64 + ((ch ^ ((row >> 1) & 3)) << 4);
                    LDM_X4(B1[0], B1[1], B1[2], B1[3], bd);
                }
                #pragma unroll
                for (int mt = 0; mt < 4; ++mt) {
                    MMA16(acc[mt][0], a[mt], B0[0], B0[2]);
                    MMA16(acc[mt][1], a[mt], B0[1], B0[3]);
                    MMA16(acc[mt][2], a[mt], B1[0], B1[2]);
                    MMA16(acc[mt][3], a[mt], B1[1], B1[3]);
                }
            }
        }
        b0 += 2; if (b0 >= NSTAGE) b0 -= NSTAGE;
    }

    #pragma unroll
    for (int mt = 0; mt < 4; ++mt) {
        #pragma unroll
        for (int hf = 0; hf < 2; ++hf) {
            int row = wm * 64 + mt * 16 + grp + hf * 8;
            int rr = m0 + row;
            if (rr < cnt) {
                int   ts = g_tokslot[e * NT + rr];
                float gt = g_gate[e * NT + rr];
                float* dst = g_y + (size_t)ts * ND + n0;
                #pragma unroll
                for (int nt = 0; nt < 4; ++nt) {
                    int col = wn * 32 + nt * 8 + 2 * tig;
                    float2 v = make_float2(acc[mt][nt][hf * 2 + 0] * gt,
                                           acc[mt][nt][hf * 2 + 1] * gt);
                    *(float2*)(dst + col) = v;
                }
            }
        }
    }
}

// out[t] = y[2t] + y[2t+1]
__global__ void combine_kernel(float* __restrict__ out) {
    int i = blockIdx.x * blockDim.x + threadIdx.x;
    if (i < NT * ND / 4) {
        int t = i >> 8, c = i & 255;
        const float4* y4 = reinterpret_cast<const float4*>(g_y);
        float4 a = y4[(size_t)(2 * t) * 256 + c];
        float4 b = y4[(size_t)(2 * t + 1) * 256 + c];
        reinterpret_cast<float4*>(out)[i] =
            make_float4(a.x + b.x, a.y + b.y, a.z + b.z, a.w + b.w);
    }
}

extern "C" void kernel_launch(void* const* d_in, const int* in_sizes, int n_in,
                              void* d_out, int out_size) {
    const float* x     = (const float*)d_in[0];
    const float* wr    = (const float*)d_in[1];
    const float* w_in  = (const float*)d_in[2];
    const float* w_out = (const float*)d_in[3];
    float* out = (float*)d_out;

    float* logits;
    if (out_size >= NT * ND + NT * NE) {
        logits = out + (size_t)NT * ND;
    } else {
        cudaGetSymbolAddress((void**)&logits, g_logits_scratch);
    }

    __half *px16, *pwin16, *pwout16;
    cudaGetSymbolAddress((void**)&px16, g_x16);
    cudaGetSymbolAddress((void**)&pwin16, g_win16);
    cudaGetSymbolAddress((void**)&pwout16, g_wout16);

    cudaFuncSetAttribute(ffn1_h, cudaFuncAttributeMaxDynamicSharedMemorySize, SMEM_BYTES);
    cudaFuncSetAttribute(ffn2_h, cudaFuncAttributeMaxDynamicSharedMemorySize, SMEM_BYTES);

    init_kernel<<<1, 32>>>();
    router_kernel<<<NT, 256>>>(x, wr, logits, px16);
    cvtw_kernel<<<2048, 256>>>(w_in, pwin16, w_out, pwout16);
    ffn1_h<<<dim3(NH / 64, NT / 128, NE), 256, SMEM_BYTES>>>();
    ffn2_h<<<dim3(ND / 128, NT / 128, NE), 256, SMEM_BYTES>>>();
    combine_kernel<<<(NT * ND / 4 + 255) / 256, 256>>>(out);
}

// round 10
// speedup vs baseline: 1.0251x; 1.0251x over previous
#include <cuda_runtime.h>
#include <cuda_fp16.h>
#include <math.h>
#include <stdint.h>

#define NT 4096      // tokens = B*S
#define ND 1024      // hidden
#define NH 512       // intermediate
#define NE 8         // experts

// ---- device scratch (static; no allocations allowed) ----
__device__ int    g_cnt[NE];
__device__ int    g_tokslot[NE * NT];
__device__ float  g_gate[NE * NT];
__device__ __half g_x16[(size_t)NT * ND];
__device__ __half g_win16[(size_t)NE * 2 * NH * ND];
__device__ __half g_wout16[(size_t)NE * ND * NH];
__device__ __half g_h16[(size_t)NE * NT * NH];
__device__ float  g_y[(size_t)NT * 2 * ND];
__device__ float  g_logits_scratch[(size_t)NT * NE];

// ======================= helpers =======================
__device__ __forceinline__ uint32_t smem_u32(const void* p) {
    uint32_t a;
    asm("{ .reg .u64 t; cvta.to.shared.u64 t, %1; cvt.u32.u64 %0, t; }" : "=r"(a) : "l"(p));
    return a;
}
#define CPA16(dst, src) asm volatile("cp.async.cg.shared.global [%0], [%1], 16;" :: "r"(dst), "l"(src))
#define CPCOMMIT()      asm volatile("cp.async.commit_group;")
#define CPWAIT(n)       asm volatile("cp.async.wait_group %0;" :: "n"(n))
#define LDM_X4(r0, r1, r2, r3, addr) \
    asm volatile("ldmatrix.sync.aligned.m8n8.x4.shared.b16 {%0,%1,%2,%3}, [%4];" \
        : "=r"(r0), "=r"(r1), "=r"(r2), "=r"(r3) : "r"(addr))
#define MMA16(d, a, b0, b1) \
    asm volatile("mma.sync.aligned.m16n8k16.row.col.f32.f16.f16.f32 " \
        "{%0,%1,%2,%3}, {%4,%5,%6,%7}, {%8,%9}, {%0,%1,%2,%3};" \
        : "+f"((d)[0]), "+f"((d)[1]), "+f"((d)[2]), "+f"((d)[3]) \
        : "r"((a)[0]), "r"((a)[1]), "r"((a)[2]), "r"((a)[3]), "r"(b0), "r"(b1))

// =====================================================================
// Merged fp32->fp16 weight convert; also zeroes g_cnt (runs before router).
// 524288 threads x exactly 6 float4 each (fully unrolled, MLP=6).
#define NWI (NE * 2 * NH * ND / 4)
#define NWO (NE * ND * NH / 4)
#define CVT_THREADS 524288
__global__ void cvtw_kernel(const float* __restrict__ win, __half* __restrict__ dwin,
                            const float* __restrict__ wout, __half* __restrict__ dwout) {
    if (blockIdx.x == 0 && threadIdx.x < NE) g_cnt[threadIdx.x] = 0;
    int tid = blockIdx.x * blockDim.x + threadIdx.x;
    #pragma unroll
    for (int u = 0; u < 6; ++u) {
        int i = tid + u * CVT_THREADS;
        const float* s; __half* d; int j;
        if (i < NWI) { s = win; d = dwin; j = i; }
        else         { s = wout; d = dwout; j = i - NWI; }
        float4 v = reinterpret_cast<const float4*>(s)[j];
        reinterpret_cast<__half2*>(d)[2 * j]     = __floats2half2_rn(v.x, v.y);
        reinterpret_cast<__half2*>(d)[2 * j + 1] = __floats2half2_rn(v.z, v.w);
    }
}

// One block per token: logits (8 warp-dots), top-2 softmax dispatch,
// AND fp16 conversion of this token's x row (row is L1-hot).
__global__ void router_kernel(const float* __restrict__ x,
                              const float* __restrict__ wr,
                              float* __restrict__ logits_out,
                              __half* __restrict__ x16) {
    int t = blockIdx.x;
    int w = threadIdx.x >> 5;
    int l = threadIdx.x & 31;
    const float* xr = x + (size_t)t * ND;
    const float* wrow = wr + w * ND;
    float s = 0.f;
    #pragma unroll 8
    for (int j = l; j < ND; j += 32) s += xr[j] * wrow[j];
    #pragma unroll
    for (int o = 16; o > 0; o >>= 1) s += __shfl_xor_sync(0xffffffffu, s, o);
    __shared__ float lg[NE];
    if (l == 0) { lg[w] = s; logits_out[(size_t)t * NE + w] = s; }

    {
        int j = threadIdx.x * 4;
        float4 v = *reinterpret_cast<const float4*>(xr + j);
        __half2* dst = reinterpret_cast<__half2*>(x16 + (size_t)t * ND + j);
        dst[0] = __floats2half2_rn(v.x, v.y);
        dst[1] = __floats2half2_rn(v.z, v.w);
    }

    __syncthreads();
    if (threadIdx.x == 0) {
        int i0 = 0; float v0 = lg[0];
        #pragma unroll
        for (int e = 1; e < NE; ++e) if (lg[e] > v0) { v0 = lg[e]; i0 = e; }
        int i1 = -1; float v1 = -INFINITY;
        #pragma unroll
        for (int e = 0; e < NE; ++e) if (e != i0 && lg[e] > v1) { v1 = lg[e]; i1 = e; }
        float e1 = expf(v1 - v0);
        float inv = 1.f / (1.f + e1);
        int p0 = atomicAdd(&g_cnt[i0], 1);
        g_tokslot[i0 * NT + p0] = t * 2;
        g_gate[i0 * NT + p0]    = inv;
        int p1 = atomicAdd(&g_cnt[i1], 1);
        g_tokslot[i1 * NT + p1] = t * 2 + 1;
        g_gate[i1 * NT + p1]    = e1 * inv;
    }
}

// Shared-mem geometry: row = 64B (32 halfs), chunk = 16B, swizzle c^=((row>>1)&3).
// Stage = A(128x32h, 8KB) + B(128x32h, 8KB) = 16KB; 3 stages = 48KB (static).
#define STAGE_BYTES 16384

// =====================================================================
// ffn1: C[128 x 128] = A(gathered x16 rows) @ B^T, fp16 mma, K = 1024.
// B tile rows interleaved per-warp (a/b halves pair thread-locally).
// LDSM addresses XOR-hoisted: addr = As + (rel ^ (ks<<5)); rel precomputed.
// Epilogue: h = silu(a)*b -> g_h16, all-register.
// =====================================================================
__global__ void __launch_bounds__(256, 2)
ffn1_h(void) {
    __shared__ __align__(128) uint8_t smem[3 * STAGE_BYTES];
    int e = blockIdx.z;
    int cnt = g_cnt[e];
    int m0 = blockIdx.y * 128;
    if (m0 >= cnt) return;
    int n0 = blockIdx.x * 64;

    uint32_t sb = smem_u32(smem);
    int t = threadIdx.x;
    int lane = t & 31, wid = t >> 5;
    int wm = wid & 1, wn = wid >> 1;          // warp grid 2(M) x 4(N)
    int grp = lane >> 2, tig = lane & 3;
    int rA = (lane & 7) + ((lane >> 3) & 1) * 8;   // ldmatrix row-in-16
    int csel = lane >> 4;                          // ldmatrix chunk select

    int lr = t >> 2;             // 0..63
    int lc = t & 3;
    int r0 = m0 + lr, r1 = r0 + 64;
    int rc0 = r0 < cnt ? r0 : cnt - 1;
    int rc1 = r1 < cnt ? r1 : cnt - 1;
    const __half* asrc0 = g_x16 + (size_t)(g_tokslot[e * NT + rc0] >> 1) * ND + lc * 8;
    const __half* asrc1 = g_x16 + (size_t)(g_tokslot[e * NT + rc1] >> 1) * ND + lc * 8;
    // interleaved B-row mapping for tile rows nn0=lr, nn1=lr+64
    int nn0 = lr, nn1 = lr + 64;
    int j0 = nn0 & 31, j1 = nn1 & 31;
    int brow0 = (j0 < 16) ? (n0 + (nn0 >> 5) * 16 + j0) : (NH + n0 + (nn0 >> 5) * 16 + j0 - 16);
    int brow1 = (j1 < 16) ? (n0 + (nn1 >> 5) * 16 + j1) : (NH + n0 + (nn1 >> 5) * 16 + j1 - 16);
    const __half* bsrc0 = g_win16 + ((size_t)e * (2 * NH) + brow0) * ND + lc * 8;
    const __half* bsrc1 = g_win16 + ((size_t)e * (2 * NH) + brow1) * ND + lc * 8;
    uint32_t swc = (uint32_t)((lc ^ ((lr >> 1) & 3)) << 4);
    uint32_t dA0 = lr * 64 + swc;
    uint32_t dA1 = dA0 + 4096;

    // hoisted LDSM relative addresses (swizzle bits 4-5; per-LDSM: 1 XOR + 1 ADD)
    uint32_t relA[4], relB0, relB1;
    #pragma unroll
    for (int mt = 0; mt < 4; ++mt) {
        int row = wm * 64 + mt * 16 + rA;
        relA[mt] = (uint32_t)(row * 64) + ((uint32_t)((((row >> 1) & 3) ^ csel)) << 4);
    }
    {
        int row = wn * 32 + rA;
        relB0 = 8192u + (uint32_t)(row * 64) + ((uint32_t)((((row >> 1) & 3) ^ csel)) << 4);
        row += 16;
        relB1 = 8192u + (uint32_t)(row * 64) + ((uint32_t)((((row >> 1) & 3) ^ csel)) << 4);
    }

    float acc[4][4][4];
    #pragma unroll
    for (int i = 0; i < 4; ++i)
        #pragma unroll
        for (int j = 0; j < 4; ++j)
            #pragma unroll
            for (int q = 0; q < 4; ++q) acc[i][j][q] = 0.f;

    #pragma unroll
    for (int s = 0; s < 2; ++s) {
        uint32_t st = sb + s * STAGE_BYTES;
        CPA16(st + dA0, asrc0 + s * 32);
        CPA16(st + dA1, asrc1 + s * 32);
        CPA16(st + 8192 + dA0, bsrc0 + s * 32);
        CPA16(st + 8192 + dA1, bsrc1 + s * 32);
        CPCOMMIT();
    }

    const int NK = ND / 32;   // 32
    int stage = 0;
    for (int kt = 0; kt < NK; ++kt) {
        if (kt < NK - 1) { CPWAIT(1); } else { CPWAIT(0); }
        __syncthreads();
        if (kt + 2 < NK) {
            uint32_t st = sb + ((kt + 2) % 3) * STAGE_BYTES;
            int off = (kt + 2) * 32;
            CPA16(st + dA0, asrc0 + off);
            CPA16(st + dA1, asrc1 + off);
            CPA16(st + 8192 + dA0, bsrc0 + off);
            CPA16(st + 8192 + dA1, bsrc1 + off);
            CPCOMMIT();
        }
        uint32_t As = sb + stage * STAGE_BYTES;
        #pragma unroll
        for (int ks = 0; ks < 2; ++ks) {
            uint32_t kx = (uint32_t)(ks << 5);
            uint32_t a[4][4], B0[4], B1[4];
            #pragma unroll
            for (int mt = 0; mt < 4; ++mt)
                LDM_X4(a[mt][0], a[mt][1], a[mt][2], a[mt][3], As + (relA[mt] ^ kx));
            LDM_X4(B0[0], B0[1], B0[2], B0[3], As + (relB0 ^ kx));
            LDM_X4(B1[0], B1[1], B1[2], B1[3], As + (relB1 ^ kx));
            #pragma unroll
            for (int mt = 0; mt < 4; ++mt) {
                MMA16(acc[mt][0], a[mt], B0[0], B0[2]);
                MMA16(acc[mt][1], a[mt], B0[1], B0[3]);
                MMA16(acc[mt][2], a[mt], B1[0], B1[2]);
                MMA16(acc[mt][3], a[mt], B1[1], B1[3]);
            }
        }
        stage = stage + 1; if (stage == 3) stage = 0;
    }

    // epilogue: acc[mt][nt] (a-cols) pairs with acc[mt][nt+2] (b-cols), nt in {0,1}.
    #pragma unroll
    for (int mt = 0; mt < 4; ++mt) {
        #pragma unroll
        for (int hf = 0; hf < 2; ++hf) {
            int row = wm * 64 + mt * 16 + grp + hf * 8;
            int rr = m0 + row;
            if (rr < cnt) {
                __half* dst = g_h16 + ((size_t)e * NT + rr) * NH + n0 + wn * 16;
                #pragma unroll
                for (int nt = 0; nt < 2; ++nt) {
                    float a0 = acc[mt][nt][hf * 2 + 0];
                    float a1 = acc[mt][nt][hf * 2 + 1];
                    float b0 = acc[mt][nt + 2][hf * 2 + 0];
                    float b1 = acc[mt][nt + 2][hf * 2 + 1];
                    float h0 = a0 / (1.f + __expf(-a0)) * b0;
                    float h1 = a1 / (1.f + __expf(-a1)) * b1;
                    *(__half2*)(dst + nt * 8 + 2 * tig) = __floats2half2_rn(h0, h1);
                }
            }
        }
    }
}

// =====================================================================
// ffn2: C[128 x 128] = g_h16 rows @ w_out16 rows^T, K = 512.
// Epilogue: gate-scale, scatter rows to g_y[tokslot].
// =====================================================================
__global__ void __launch_bounds__(256, 2)
ffn2_h(void) {
    __shared__ __align__(128) uint8_t smem[3 * STAGE_BYTES];
    int e = blockIdx.z;
    int cnt = g_cnt[e];
    int m0 = blockIdx.y * 128;
    if (m0 >= cnt) return;
    int n0 = blockIdx.x * 128;

    uint32_t sb = smem_u32(smem);
    int t = threadIdx.x;
    int lane = t & 31, wid = t >> 5;
    int wm = wid & 1, wn = wid >> 1;
    int grp = lane >> 2, tig = lane & 3;
    int rA = (lane & 7) + ((lane >> 3) & 1) * 8;
    int csel = lane >> 4;

    int lr = t >> 2;
    int lc = t & 3;
    int r0 = m0 + lr, r1 = r0 + 64;
    int rc0 = r0 < cnt ? r0 : cnt - 1;
    int rc1 = r1 < cnt ? r1 : cnt - 1;
    const __half* asrc0 = g_h16 + ((size_t)e * NT + rc0) * NH + lc * 8;
    const __half* asrc1 = g_h16 + ((size_t)e * NT + rc1) * NH + lc * 8;
    const __half* bsrc0 = g_wout16 + ((size_t)e * ND + n0 + lr) * NH + lc * 8;
    const __half* bsrc1 = g_wout16 + ((size_t)e * ND + n0 + lr + 64) * NH + lc * 8;
    uint32_t swc = (uint32_t)((lc ^ ((lr >> 1) & 3)) << 4);
    uint32_t dA0 = lr * 64 + swc;
    uint32_t dA1 = dA0 + 4096;

    uint32_t relA[4], relB0, relB1;
    #pragma unroll
    for (int mt = 0; mt < 4; ++mt) {
        int row = wm * 64 + mt * 16 + rA;
        relA[mt] = (uint32_t)(row * 64) + ((uint32_t)((((row >> 1) & 3) ^ csel)) << 4);
    }
    {
        int row = wn * 32 + rA;
        relB0 = 8192u + (uint32_t)(row * 64) + ((uint32_t)((((row >> 1) & 3) ^ csel)) << 4);
        row += 16;
        relB1 = 8192u + (uint32_t)(row * 64) + ((uint32_t)((((row >> 1) & 3) ^ csel)) << 4);
    }

    float acc[4][4][4];
    #pragma unroll
    for (int i = 0; i < 4; ++i)
        #pragma unroll
        for (int j = 0; j < 4; ++j)
            #pragma unroll
            for (int q = 0; q < 4; ++q) acc[i][j][q] = 0.f;

    #pragma unroll
    for (int s = 0; s < 2; ++s) {
        uint32_t st = sb + s * STAGE_BYTES;
        CPA16(st + dA0, asrc0 + s * 32);
        CPA16(st + dA1, asrc1 + s * 32);
        CPA16(st + 8192 + dA0, bsrc0 + s * 32);
        CPA16(st + 8192 + dA1, bsrc1 + s * 32);
        CPCOMMIT();
    }

    const int NK = NH / 32;   // 16
    int stage = 0;
    for (int kt = 0; kt < NK; ++kt) {
        if (kt < NK - 1) { CPWAIT(1); } else { CPWAIT(0); }
        __syncthreads();
        if (kt + 2 < NK) {
            uint32_t st = sb + ((kt + 2) % 3) * STAGE_BYTES;
            int off = (kt + 2) * 32;
            CPA16(st + dA0, asrc0 + off);
            CPA16(st + dA1, asrc1 + off);
            CPA16(st + 8192 + dA0, bsrc0 + off);
            CPA16(st + 8192 + dA1, bsrc1 + off);
            CPCOMMIT();
        }
        uint32_t As = sb + stage * STAGE_BYTES;
        #pragma unroll
        for (int ks = 0; ks < 2; ++ks) {
            uint32_t kx = (uint32_t)(ks << 5);
            uint32_t a[4][4], B0[4], B1[4];
            #pragma unroll
            for (int mt = 0; mt < 4; ++mt)
                LDM_X4(a[mt][0], a[mt][1], a[mt][2], a[mt][3], As + (relA[mt] ^ kx));
            LDM_X4(B0[0], B0[1], B0[2], B0[3], As + (relB0 ^ kx));
            LDM_X4(B1[0], B1[1], B1[2], B1[3], As + (relB1 ^ kx));
            #pragma unroll
            for (int mt = 0; mt < 4; ++mt) {
                MMA16(acc[mt][0], a[mt], B0[0], B0[2]);
                MMA16(acc[mt][1], a[mt], B0[1], B0[3]);
                MMA16(acc[mt][2], a[mt], B1[0], B1[2]);
                MMA16(acc[mt][3], a[mt], B1[1], B1[3]);
            }
        }
        stage = stage + 1; if (stage == 3) stage = 0;
    }

    #pragma unroll
    for (int mt = 0; mt < 4; ++mt) {
        #pragma unroll
        for (int hf = 0; hf < 2; ++hf) {
            int row = wm * 64 + mt * 16 + grp + hf * 8;
            int rr = m0 + row;
            if (rr < cnt) {
                int   ts = g_tokslot[e * NT + rr];
                float gt = g_gate[e * NT + rr];
                float* dst = g_y + (size_t)ts * ND + n0;
                #pragma unroll
                for (int nt = 0; nt < 4; ++nt) {
                    int col = wn * 32 + nt * 8 + 2 * tig;
                    float2 v = make_float2(acc[mt][nt][hf * 2 + 0] * gt,
                                           acc[mt][nt][hf * 2 + 1] * gt);
                    *(float2*)(dst + col) = v;
                }
            }
        }
    }
}

// out[t] = y[2t] + y[2t+1]
__global__ void combine_kernel(float* __restrict__ out) {
    int i = blockIdx.x * blockDim.x + threadIdx.x;
    if (i < NT * ND / 4) {
        int t = i >> 8, c = i & 255;
        const float4* y4 = reinterpret_cast<const float4*>(g_y);
        float4 a = y4[(size_t)(2 * t) * 256 + c];
        float4 b = y4[(size_t)(2 * t + 1) * 256 + c];
        reinterpret_cast<float4*>(out)[i] =
            make_float4(a.x + b.x, a.y + b.y, a.z + b.z, a.w + b.w);
    }
}

extern "C" void kernel_launch(void* const* d_in, const int* in_sizes, int n_in,
                              void* d_out, int out_size) {
    const float* x     = (const float*)d_in[0];
    const float* wr    = (const float*)d_in[1];
    const float* w_in  = (const float*)d_in[2];
    const float* w_out = (const float*)d_in[3];
    float* out = (float*)d_out;

    float* logits;
    if (out_size >= NT * ND + NT * NE) {
        logits = out + (size_t)NT * ND;
    } else {
        cudaGetSymbolAddress((void**)&logits, g_logits_scratch);
    }

    __half *px16, *pwin16, *pwout16;
    cudaGetSymbolAddress((void**)&px16, g_x16);
    cudaGetSymbolAddress((void**)&pwin16, g_win16);
    cudaGetSymbolAddress((void**)&pwout16, g_wout16);

    cvtw_kernel<<<CVT_THREADS / 256, 256>>>(w_in, pwin16, w_out, pwout16);
    router_kernel<<<NT, 256>>>(x, wr, logits, px16);
    ffn1_h<<<dim3(NH / 64, NT / 128, NE), 256>>>();
    ffn2_h<<<dim3(ND / 128, NT / 128, NE), 256>>>();
    combine_kernel<<<(NT * ND / 4 + 255) / 256, 256>>>(out);
}

// round 11
// speedup vs baseline: 1.0739x; 1.0476x over previous
#include <cuda_runtime.h>
#include <cuda_fp16.h>
#include <math.h>
#include <stdint.h>

#define NT 4096      // tokens = B*S
#define ND 1024      // hidden
#define NH 512       // intermediate
#define NE 8         // experts

// ---- device scratch (static; no allocations allowed) ----
__device__ int    g_cnt[NE];          // zero-init at load; re-zeroed by combine_kernel each call
__device__ int    g_tokslot[NE * NT];
__device__ float  g_gate[NE * NT];
__device__ __half g_x16[(size_t)NT * ND];
__device__ __half g_win16[(size_t)NE * 2 * NH * ND];
__device__ __half g_wout16[(size_t)NE * ND * NH];
__device__ __half g_h16[(size_t)NE * NT * NH];
__device__ float  g_y[(size_t)NT * 2 * ND];
__device__ float  g_logits_scratch[(size_t)NT * NE];

// ======================= helpers =======================
__device__ __forceinline__ uint32_t smem_u32(const void* p) {
    uint32_t a;
    asm("{ .reg .u64 t; cvta.to.shared.u64 t, %1; cvt.u32.u64 %0, t; }" : "=r"(a) : "l"(p));
    return a;
}
#define CPA16(dst, src) asm volatile("cp.async.cg.shared.global [%0], [%1], 16;" :: "r"(dst), "l"(src))
#define CPCOMMIT()      asm volatile("cp.async.commit_group;")
#define CPWAIT(n)       asm volatile("cp.async.wait_group %0;" :: "n"(n))
#define LDM_X4(r0, r1, r2, r3, addr) \
    asm volatile("ldmatrix.sync.aligned.m8n8.x4.shared.b16 {%0,%1,%2,%3}, [%4];" \
        : "=r"(r0), "=r"(r1), "=r"(r2), "=r"(r3) : "r"(addr))
#define MMA16(d, a, b0, b1) \
    asm volatile("mma.sync.aligned.m16n8k16.row.col.f32.f16.f16.f32 " \
        "{%0,%1,%2,%3}, {%4,%5,%6,%7}, {%8,%9}, {%0,%1,%2,%3};" \
        : "+f"((d)[0]), "+f"((d)[1]), "+f"((d)[2]), "+f"((d)[3]) \
        : "r"((a)[0]), "r"((a)[1]), "r"((a)[2]), "r"((a)[3]), "r"(b0), "r"(b1))

// =====================================================================
// prep_kernel: blocks [0, NT) = router (+x fp16 convert);
//              blocks [NT, NT + CVT_BLOCKS) = weight fp32->fp16 convert.
// Router and weight-convert are independent -> they overlap in one launch.
// g_cnt is zeroed BEFORE this kernel (static init on first call; combine
// re-zeroes at the end of every call for graph replays).
#define NWI (NE * 2 * NH * ND / 4)
#define NWO (NE * ND * NH / 4)
#define CVT_THREADS 524288
#define CVT_BLOCKS (CVT_THREADS / 256)
__global__ void prep_kernel(const float* __restrict__ x,
                            const float* __restrict__ wr,
                            float* __restrict__ logits_out,
                            __half* __restrict__ x16,
                            const float* __restrict__ win, __half* __restrict__ dwin,
                            const float* __restrict__ wout, __half* __restrict__ dwout) {
    if (blockIdx.x < NT) {
        // ---- router + x convert ----
        int t = blockIdx.x;
        int w = threadIdx.x >> 5;
        int l = threadIdx.x & 31;
        const float* xr = x + (size_t)t * ND;
        const float* wrow = wr + w * ND;
        float s = 0.f;
        #pragma unroll 8
        for (int j = l; j < ND; j += 32) s += xr[j] * wrow[j];
        #pragma unroll
        for (int o = 16; o > 0; o >>= 1) s += __shfl_xor_sync(0xffffffffu, s, o);
        __shared__ float lg[NE];
        if (l == 0) { lg[w] = s; logits_out[(size_t)t * NE + w] = s; }

        {
            int j = threadIdx.x * 4;
            float4 v = *reinterpret_cast<const float4*>(xr + j);
            __half2* dst = reinterpret_cast<__half2*>(x16 + (size_t)t * ND + j);
            dst[0] = __floats2half2_rn(v.x, v.y);
            dst[1] = __floats2half2_rn(v.z, v.w);
        }

        __syncthreads();
        if (threadIdx.x == 0) {
            int i0 = 0; float v0 = lg[0];
            #pragma unroll
            for (int e = 1; e < NE; ++e) if (lg[e] > v0) { v0 = lg[e]; i0 = e; }
            int i1 = -1; float v1 = -INFINITY;
            #pragma unroll
            for (int e = 0; e < NE; ++e) if (e != i0 && lg[e] > v1) { v1 = lg[e]; i1 = e; }
            float e1 = expf(v1 - v0);
            float inv = 1.f / (1.f + e1);
            int p0 = atomicAdd(&g_cnt[i0], 1);
            g_tokslot[i0 * NT + p0] = t * 2;
            g_gate[i0 * NT + p0]    = inv;
            int p1 = atomicAdd(&g_cnt[i1], 1);
            g_tokslot[i1 * NT + p1] = t * 2 + 1;
            g_gate[i1 * NT + p1]    = e1 * inv;
        }
    } else {
        // ---- weight convert: exactly 6 float4 per thread ----
        int tid = (blockIdx.x - NT) * blockDim.x + threadIdx.x;
        #pragma unroll
        for (int u = 0; u < 6; ++u) {
            int i = tid + u * CVT_THREADS;
            const float* s; __half* d; int j;
            if (i < NWI) { s = win; d = dwin; j = i; }
            else         { s = wout; d = dwout; j = i - NWI; }
            float4 v = reinterpret_cast<const float4*>(s)[j];
            reinterpret_cast<__half2*>(d)[2 * j]     = __floats2half2_rn(v.x, v.y);
            reinterpret_cast<__half2*>(d)[2 * j + 1] = __floats2half2_rn(v.z, v.w);
        }
    }
}

// Shared-mem geometry: row = 64B (32 halfs), chunk = 16B, swizzle c^=((row>>1)&3).
// Stage = A(128x32h, 8KB) + B(128x32h, 8KB) = 16KB; 3 stages = 48KB (static).
#define STAGE_BYTES 16384

// =====================================================================
// ffn1: C[128 x 128] = A(gathered x16 rows) @ B^T, fp16 mma, K = 1024.
// B tile rows interleaved per-warp (a/b halves pair thread-locally).
// LDSM addresses XOR-hoisted: addr = As + (rel ^ (ks<<5)); rel precomputed.
// Epilogue: h = silu(a)*b -> g_h16, all-register.
// =====================================================================
__global__ void __launch_bounds__(256, 2)
ffn1_h(void) {
    __shared__ __align__(128) uint8_t smem[3 * STAGE_BYTES];
    int e = blockIdx.z;
    int cnt = g_cnt[e];
    int m0 = blockIdx.y * 128;
    if (m0 >= cnt) return;
    int n0 = blockIdx.x * 64;

    uint32_t sb = smem_u32(smem);
    int t = threadIdx.x;
    int lane = t & 31, wid = t >> 5;
    int wm = wid & 1, wn = wid >> 1;          // warp grid 2(M) x 4(N)
    int grp = lane >> 2, tig = lane & 3;
    int rA = (lane & 7) + ((lane >> 3) & 1) * 8;   // ldmatrix row-in-16
    int csel = lane >> 4;                          // ldmatrix chunk select

    int lr = t >> 2;             // 0..63
    int lc = t & 3;
    int r0 = m0 + lr, r1 = r0 + 64;
    int rc0 = r0 < cnt ? r0 : cnt - 1;
    int rc1 = r1 < cnt ? r1 : cnt - 1;
    const __half* asrc0 = g_x16 + (size_t)(g_tokslot[e * NT + rc0] >> 1) * ND + lc * 8;
    const __half* asrc1 = g_x16 + (size_t)(g_tokslot[e * NT + rc1] >> 1) * ND + lc * 8;
    // interleaved B-row mapping for tile rows nn0=lr, nn1=lr+64
    int nn0 = lr, nn1 = lr + 64;
    int j0 = nn0 & 31, j1 = nn1 & 31;
    int brow0 = (j0 < 16) ? (n0 + (nn0 >> 5) * 16 + j0) : (NH + n0 + (nn0 >> 5) * 16 + j0 - 16);
    int brow1 = (j1 < 16) ? (n0 + (nn1 >> 5) * 16 + j1) : (NH + n0 + (nn1 >> 5) * 16 + j1 - 16);
    const __half* bsrc0 = g_win16 + ((size_t)e * (2 * NH) + brow0) * ND + lc * 8;
    const __half* bsrc1 = g_win16 + ((size_t)e * (2 * NH) + brow1) * ND + lc * 8;
    uint32_t swc = (uint32_t)((lc ^ ((lr >> 1) & 3)) << 4);
    uint32_t dA0 = lr * 64 + swc;
    uint32_t dA1 = dA0 + 4096;

    // hoisted LDSM relative addresses (swizzle bits 4-5; per-LDSM: 1 XOR + 1 ADD)
    uint32_t relA[4], relB0, relB1;
    #pragma unroll
    for (int mt = 0; mt < 4; ++mt) {
        int row = wm * 64 + mt * 16 + rA;
        relA[mt] = (uint32_t)(row * 64) + ((uint32_t)((((row >> 1) & 3) ^ csel)) << 4);
    }
    {
        int row = wn * 32 + rA;
        relB0 = 8192u + (uint32_t)(row * 64) + ((uint32_t)((((row >> 1) & 3) ^ csel)) << 4);
        row += 16;
        relB1 = 8192u + (uint32_t)(row * 64) + ((uint32_t)((((row >> 1) & 3) ^ csel)) << 4);
    }

    float acc[4][4][4];
    #pragma unroll
    for (int i = 0; i < 4; ++i)
        #pragma unroll
        for (int j = 0; j < 4; ++j)
            #pragma unroll
            for (int q = 0; q < 4; ++q) acc[i][j][q] = 0.f;

    #pragma unroll
    for (int s = 0; s < 2; ++s) {
        uint32_t st = sb + s * STAGE_BYTES;
        CPA16(st + dA0, asrc0 + s * 32);
        CPA16(st + dA1, asrc1 + s * 32);
        CPA16(st + 8192 + dA0, bsrc0 + s * 32);
        CPA16(st + 8192 + dA1, bsrc1 + s * 32);
        CPCOMMIT();
    }

    const int NK = ND / 32;   // 32
    int stage = 0;
    for (int kt = 0; kt < NK; ++kt) {
        if (kt < NK - 1) { CPWAIT(1); } else { CPWAIT(0); }
        __syncthreads();
        if (kt + 2 < NK) {
            uint32_t st = sb + ((kt + 2) % 3) * STAGE_BYTES;
            int off = (kt + 2) * 32;
            CPA16(st + dA0, asrc0 + off);
            CPA16(st + dA1, asrc1 + off);
            CPA16(st + 8192 + dA0, bsrc0 + off);
            CPA16(st + 8192 + dA1, bsrc1 + off);
            CPCOMMIT();
        }
        uint32_t As = sb + stage * STAGE_BYTES;
        #pragma unroll
        for (int ks = 0; ks < 2; ++ks) {
            uint32_t kx = (uint32_t)(ks << 5);
            uint32_t a[4][4], B0[4], B1[4];
            #pragma unroll
            for (int mt = 0; mt < 4; ++mt)
                LDM_X4(a[mt][0], a[mt][1], a[mt][2], a[mt][3], As + (relA[mt] ^ kx));
            LDM_X4(B0[0], B0[1], B0[2], B0[3], As + (relB0 ^ kx));
            LDM_X4(B1[0], B1[1], B1[2], B1[3], As + (relB1 ^ kx));
            #pragma unroll
            for (int mt = 0; mt < 4; ++mt) {
                MMA16(acc[mt][0], a[mt], B0[0], B0[2]);
                MMA16(acc[mt][1], a[mt], B0[1], B0[3]);
                MMA16(acc[mt][2], a[mt], B1[0], B1[2]);
                MMA16(acc[mt][3], a[mt], B1[1], B1[3]);
            }
        }
        stage = stage + 1; if (stage == 3) stage = 0;
    }

    // epilogue: acc[mt][nt] (a-cols) pairs with acc[mt][nt+2] (b-cols), nt in {0,1}.
    #pragma unroll
    for (int mt = 0; mt < 4; ++mt) {
        #pragma unroll
        for (int hf = 0; hf < 2; ++hf) {
            int row = wm * 64 + mt * 16 + grp + hf * 8;
            int rr = m0 + row;
            if (rr < cnt) {
                __half* dst = g_h16 + ((size_t)e * NT + rr) * NH + n0 + wn * 16;
                #pragma unroll
                for (int nt = 0; nt < 2; ++nt) {
                    float a0 = acc[mt][nt][hf * 2 + 0];
                    float a1 = acc[mt][nt][hf * 2 + 1];
                    float b0 = acc[mt][nt + 2][hf * 2 + 0];
                    float b1 = acc[mt][nt + 2][hf * 2 + 1];
                    float h0 = a0 / (1.f + __expf(-a0)) * b0;
                    float h1 = a1 / (1.f + __expf(-a1)) * b1;
                    *(__half2*)(dst + nt * 8 + 2 * tig) = __floats2half2_rn(h0, h1);
                }
            }
        }
    }
}

// =====================================================================
// ffn2: C[128 x 128] = g_h16 rows @ w_out16 rows^T, K = 512.
// Epilogue: gate-scale, scatter rows to g_y[tokslot].
// =====================================================================
__global__ void __launch_bounds__(256, 2)
ffn2_h(void) {
    __shared__ __align__(128) uint8_t smem[3 * STAGE_BYTES];
    int e = blockIdx.z;
    int cnt = g_cnt[e];
    int m0 = blockIdx.y * 128;
    if (m0 >= cnt) return;
    int n0 = blockIdx.x * 128;

    uint32_t sb = smem_u32(smem);
    int t = threadIdx.x;
    int lane = t & 31, wid = t >> 5;
    int wm = wid & 1, wn = wid >> 1;
    int grp = lane >> 2, tig = lane & 3;
    int rA = (lane & 7) + ((lane >> 3) & 1) * 8;
    int csel = lane >> 4;

    int lr = t >> 2;
    int lc = t & 3;
    int r0 = m0 + lr, r1 = r0 + 64;
    int rc0 = r0 < cnt ? r0 : cnt - 1;
    int rc1 = r1 < cnt ? r1 : cnt - 1;
    const __half* asrc0 = g_h16 + ((size_t)e * NT + rc0) * NH + lc * 8;
    const __half* asrc1 = g_h16 + ((size_t)e * NT + rc1) * NH + lc * 8;
    const __half* bsrc0 = g_wout16 + ((size_t)e * ND + n0 + lr) * NH + lc * 8;
    const __half* bsrc1 = g_wout16 + ((size_t)e * ND + n0 + lr + 64) * NH + lc * 8;
    uint32_t swc = (uint32_t)((lc ^ ((lr >> 1) & 3)) << 4);
    uint32_t dA0 = lr * 64 + swc;
    uint32_t dA1 = dA0 + 4096;

    uint32_t relA[4], relB0, relB1;
    #pragma unroll
    for (int mt = 0; mt < 4; ++mt) {
        int row = wm * 64 + mt * 16 + rA;
        relA[mt] = (uint32_t)(row * 64) + ((uint32_t)((((row >> 1) & 3) ^ csel)) << 4);
    }
    {
        int row = wn * 32 + rA;
        relB0 = 8192u + (uint32_t)(row * 64) + ((uint32_t)((((row >> 1) & 3) ^ csel)) << 4);
        row += 16;
        relB1 = 8192u + (uint32_t)(row * 64) + ((uint32_t)((((row >> 1) & 3) ^ csel)) << 4);
    }

    float acc[4][4][4];
    #pragma unroll
    for (int i = 0; i < 4; ++i)
        #pragma unroll
        for (int j = 0; j < 4; ++j)
            #pragma unroll
            for (int q = 0; q < 4; ++q) acc[i][j][q] = 0.f;

    #pragma unroll
    for (int s = 0; s < 2; ++s) {
        uint32_t st = sb + s * STAGE_BYTES;
        CPA16(st + dA0, asrc0 + s * 32);
        CPA16(st + dA1, asrc1 + s * 32);
        CPA16(st + 8192 + dA0, bsrc0 + s * 32);
        CPA16(st + 8192 + dA1, bsrc1 + s * 32);
        CPCOMMIT();
    }

    const int NK = NH / 32;   // 16
    int stage = 0;
    for (int kt = 0; kt < NK; ++kt) {
        if (kt < NK - 1) { CPWAIT(1); } else { CPWAIT(0); }
        __syncthreads();
        if (kt + 2 < NK) {
            uint32_t st = sb + ((kt + 2) % 3) * STAGE_BYTES;
            int off = (kt + 2) * 32;
            CPA16(st + dA0, asrc0 + off);
            CPA16(st + dA1, asrc1 + off);
            CPA16(st + 8192 + dA0, bsrc0 + off);
            CPA16(st + 8192 + dA1, bsrc1 + off);
            CPCOMMIT();
        }
        uint32_t As = sb + stage * STAGE_BYTES;
        #pragma unroll
        for (int ks = 0; ks < 2; ++ks) {
            uint32_t kx = (uint32_t)(ks << 5);
            uint32_t a[4][4], B0[4], B1[4];
            #pragma unroll
            for (int mt = 0; mt < 4; ++mt)
                LDM_X4(a[mt][0], a[mt][1], a[mt][2], a[mt][3], As + (relA[mt] ^ kx));
            LDM_X4(B0[0], B0[1], B0[2], B0[3], As + (relB0 ^ kx));
            LDM_X4(B1[0], B1[1], B1[2], B1[3], As + (relB1 ^ kx));
            #pragma unroll
            for (int mt = 0; mt < 4; ++mt) {
                MMA16(acc[mt][0], a[mt], B0[0], B0[2]);
                MMA16(acc[mt][1], a[mt], B0[1], B0[3]);
                MMA16(acc[mt][2], a[mt], B1[0], B1[2]);
                MMA16(acc[mt][3], a[mt], B1[1], B1[3]);
            }
        }
        stage = stage + 1; if (stage == 3) stage = 0;
    }

    #pragma unroll
    for (int mt = 0; mt < 4; ++mt) {
        #pragma unroll
        for (int hf = 0; hf < 2; ++hf) {
            int row = wm * 64 + mt * 16 + grp + hf * 8;
            int rr = m0 + row;
            if (rr < cnt) {
                int   ts = g_tokslot[e * NT + rr];
                float gt = g_gate[e * NT + rr];
                float* dst = g_y + (size_t)ts * ND + n0;
                #pragma unroll
                for (int nt = 0; nt < 4; ++nt) {
                    int col = wn * 32 + nt * 8 + 2 * tig;
                    float2 v = make_float2(acc[mt][nt][hf * 2 + 0] * gt,
                                           acc[mt][nt][hf * 2 + 1] * gt);
                    *(float2*)(dst + col) = v;
                }
            }
        }
    }
}

// out[t] = y[2t] + y[2t+1]; also re-zeroes g_cnt for the next graph replay
// (runs strictly after ffn2's last read of g_cnt).
__global__ void combine_kernel(float* __restrict__ out) {
    if (blockIdx.x == 0 && threadIdx.x < NE) g_cnt[threadIdx.x] = 0;
    int i = blockIdx.x * blockDim.x + threadIdx.x;
    if (i < NT * ND / 4) {
        int t = i >> 8, c = i & 255;
        const float4* y4 = reinterpret_cast<const float4*>(g_y);
        float4 a = y4[(size_t)(2 * t) * 256 + c];
        float4 b = y4[(size_t)(2 * t + 1) * 256 + c];
        reinterpret_cast<float4*>(out)[i] =
            make_float4(a.x + b.x, a.y + b.y, a.z + b.z, a.w + b.w);
    }
}

extern "C" void kernel_launch(void* const* d_in, const int* in_sizes, int n_in,
                              void* d_out, int out_size) {
    const float* x     = (const float*)d_in[0];
    const float* wr    = (const float*)d_in[1];
    const float* w_in  = (const float*)d_in[2];
    const float* w_out = (const float*)d_in[3];
    float* out = (float*)d_out;

    float* logits;
    if (out_size >= NT * ND + NT * NE) {
        logits = out + (size_t)NT * ND;
    } else {
        cudaGetSymbolAddress((void**)&logits, g_logits_scratch);
    }

    __half *px16, *pwin16, *pwout16;
    cudaGetSymbolAddress((void**)&px16, g_x16);
    cudaGetSymbolAddress((void**)&pwin16, g_win16);
    cudaGetSymbolAddress((void**)&pwout16, g_wout16);

    prep_kernel<<<NT + CVT_BLOCKS, 256>>>(x, wr, logits, px16,
                                          w_in, pwin16, w_out, pwout16);
    ffn1_h<<<dim3(NH / 64, NT / 128, NE), 256>>>();
    ffn2_h<<<dim3(ND / 128, NT / 128, NE), 256>>>();
    combine_kernel<<<(NT * ND / 4 + 255) / 256, 256>>>(out);
}

// round 12
// speedup vs baseline: 1.0903x; 1.0153x over previous
#include <cuda_runtime.h>
#include <cuda_fp16.h>
#include <math.h>
#include <stdint.h>

#define NT 4096      // tokens = B*S
#define ND 1024      // hidden
#define NH 512       // intermediate
#define NE 8         // experts

// ---- device scratch (static; no allocations allowed) ----
__device__ int    g_cnt[NE];          // zero-init at load; re-zeroed by combine_kernel each call
__device__ int    g_tokslot[NE * NT];
__device__ float  g_gate[NE * NT];
__device__ __half g_x16[(size_t)NT * ND];
__device__ __half g_win16[(size_t)NE * 2 * NH * ND];
__device__ __half g_wout16[(size_t)NE * ND * NH];
__device__ __half g_h16[(size_t)NE * NT * NH];
__device__ float  g_y[(size_t)NT * 2 * ND];
__device__ float  g_logits_scratch[(size_t)NT * NE];

// ======================= helpers =======================
__device__ __forceinline__ uint32_t smem_u32(const void* p) {
    uint32_t a;
    asm("{ .reg .u64 t; cvta.to.shared.u64 t, %1; cvt.u32.u64 %0, t; }" : "=r"(a) : "l"(p));
    return a;
}
#define CPA16(dst, src) asm volatile("cp.async.cg.shared.global [%0], [%1], 16;" :: "r"(dst), "l"(src))
#define CPCOMMIT()      asm volatile("cp.async.commit_group;")
#define CPWAIT(n)       asm volatile("cp.async.wait_group %0;" :: "n"(n))
#define LDM_X4(r0, r1, r2, r3, addr) \
    asm volatile("ldmatrix.sync.aligned.m8n8.x4.shared.b16 {%0,%1,%2,%3}, [%4];" \
        : "=r"(r0), "=r"(r1), "=r"(r2), "=r"(r3) : "r"(addr))
#define MMA16(d, a, b0, b1) \
    asm volatile("mma.sync.aligned.m16n8k16.row.col.f32.f16.f16.f32 " \
        "{%0,%1,%2,%3}, {%4,%5,%6,%7}, {%8,%9}, {%0,%1,%2,%3};" \
        : "+f"((d)[0]), "+f"((d)[1]), "+f"((d)[2]), "+f"((d)[3]) \
        : "r"((a)[0]), "r"((a)[1]), "r"((a)[2]), "r"((a)[3]), "r"(b0), "r"(b1))

// =====================================================================
// prep_kernel: blocks [0, NT) = router (+x fp16 convert);
//              blocks [NT, NT + CVT_BLOCKS) = weight fp32->fp16 convert.
#define NWI (NE * 2 * NH * ND / 4)
#define NWO (NE * ND * NH / 4)
#define CVT_THREADS 524288
#define CVT_BLOCKS (CVT_THREADS / 256)
__global__ void prep_kernel(const float* __restrict__ x,
                            const float* __restrict__ wr,
                            float* __restrict__ logits_out,
                            __half* __restrict__ x16,
                            const float* __restrict__ win, __half* __restrict__ dwin,
                            const float* __restrict__ wout, __half* __restrict__ dwout) {
    if (blockIdx.x < NT) {
        // ---- router + x convert ----
        int t = blockIdx.x;
        int w = threadIdx.x >> 5;
        int l = threadIdx.x & 31;
        const float* xr = x + (size_t)t * ND;
        const float* wrow = wr + w * ND;
        float s = 0.f;
        #pragma unroll 8
        for (int j = l; j < ND; j += 32) s += xr[j] * wrow[j];
        #pragma unroll
        for (int o = 16; o > 0; o >>= 1) s += __shfl_xor_sync(0xffffffffu, s, o);
        __shared__ float lg[NE];
        if (l == 0) { lg[w] = s; logits_out[(size_t)t * NE + w] = s; }

        {
            int j = threadIdx.x * 4;
            float4 v = *reinterpret_cast<const float4*>(xr + j);
            __half2* dst = reinterpret_cast<__half2*>(x16 + (size_t)t * ND + j);
            dst[0] = __floats2half2_rn(v.x, v.y);
            dst[1] = __floats2half2_rn(v.z, v.w);
        }

        __syncthreads();
        if (threadIdx.x == 0) {
            int i0 = 0; float v0 = lg[0];
            #pragma unroll
            for (int e = 1; e < NE; ++e) if (lg[e] > v0) { v0 = lg[e]; i0 = e; }
            int i1 = -1; float v1 = -INFINITY;
            #pragma unroll
            for (int e = 0; e < NE; ++e) if (e != i0 && lg[e] > v1) { v1 = lg[e]; i1 = e; }
            float e1 = expf(v1 - v0);
            float inv = 1.f / (1.f + e1);
            int p0 = atomicAdd(&g_cnt[i0], 1);
            g_tokslot[i0 * NT + p0] = t * 2;
            g_gate[i0 * NT + p0]    = inv;
            int p1 = atomicAdd(&g_cnt[i1], 1);
            g_tokslot[i1 * NT + p1] = t * 2 + 1;
            g_gate[i1 * NT + p1]    = e1 * inv;
        }
    } else {
        // ---- weight convert: exactly 6 float4 per thread ----
        int tid = (blockIdx.x - NT) * blockDim.x + threadIdx.x;
        #pragma unroll
        for (int u = 0; u < 6; ++u) {
            int i = tid + u * CVT_THREADS;
            const float* s; __half* d; int j;
            if (i < NWI) { s = win; d = dwin; j = i; }
            else         { s = wout; d = dwout; j = i - NWI; }
            float4 v = reinterpret_cast<const float4*>(s)[j];
            reinterpret_cast<__half2*>(d)[2 * j]     = __floats2half2_rn(v.x, v.y);
            reinterpret_cast<__half2*>(d)[2 * j + 1] = __floats2half2_rn(v.z, v.w);
        }
    }
}

// Shared-mem geometry: row = 64B (32 halfs), chunk = 16B, swizzle c^=((row>>1)&3).
// Stage = A(128x32h, 8KB) + B(128x32h, 8KB) = 16KB; 3 stages = 48KB (static).
#define STAGE_BYTES 16384

// =====================================================================
// ffn1: C[128 x 128] = A(gathered x16 rows) @ B^T, fp16 mma, K = 1024.
// B tile rows interleaved per-warp (a/b halves pair thread-locally).
// Both ks-halves' B fragments hoisted right after the sync (ks1 MMA burst
// never waits on fresh B-LDSM; A-loads of ks1 overlap ks0 MMA tail).
// Epilogue: h = silu(a)*b -> g_h16, all-register.
// =====================================================================
__global__ void __launch_bounds__(256, 2)
ffn1_h(void) {
    __shared__ __align__(128) uint8_t smem[3 * STAGE_BYTES];
    int e = blockIdx.z;
    int cnt = g_cnt[e];
    int m0 = blockIdx.y * 128;
    if (m0 >= cnt) return;
    int n0 = blockIdx.x * 64;

    uint32_t sb = smem_u32(smem);
    int t = threadIdx.x;
    int lane = t & 31, wid = t >> 5;
    int wm = wid & 1, wn = wid >> 1;          // warp grid 2(M) x 4(N)
    int grp = lane >> 2, tig = lane & 3;
    int rA = (lane & 7) + ((lane >> 3) & 1) * 8;   // ldmatrix row-in-16
    int csel = lane >> 4;                          // ldmatrix chunk select

    int lr = t >> 2;             // 0..63
    int lc = t & 3;
    int r0 = m0 + lr, r1 = r0 + 64;
    int rc0 = r0 < cnt ? r0 : cnt - 1;
    int rc1 = r1 < cnt ? r1 : cnt - 1;
    const __half* asrc0 = g_x16 + (size_t)(g_tokslot[e * NT + rc0] >> 1) * ND + lc * 8;
    const __half* asrc1 = g_x16 + (size_t)(g_tokslot[e * NT + rc1] >> 1) * ND + lc * 8;
    // interleaved B-row mapping for tile rows nn0=lr, nn1=lr+64
    int nn0 = lr, nn1 = lr + 64;
    int j0 = nn0 & 31, j1 = nn1 & 31;
    int brow0 = (j0 < 16) ? (n0 + (nn0 >> 5) * 16 + j0) : (NH + n0 + (nn0 >> 5) * 16 + j0 - 16);
    int brow1 = (j1 < 16) ? (n0 + (nn1 >> 5) * 16 + j1) : (NH + n0 + (nn1 >> 5) * 16 + j1 - 16);
    const __half* bsrc0 = g_win16 + ((size_t)e * (2 * NH) + brow0) * ND + lc * 8;
    const __half* bsrc1 = g_win16 + ((size_t)e * (2 * NH) + brow1) * ND + lc * 8;
    uint32_t swc = (uint32_t)((lc ^ ((lr >> 1) & 3)) << 4);
    uint32_t dA0 = lr * 64 + swc;
    uint32_t dA1 = dA0 + 4096;

    // hoisted LDSM relative addresses (swizzle bits 4-5; per-LDSM: 1 XOR + 1 ADD)
    uint32_t relA[4], relB0, relB1;
    #pragma unroll
    for (int mt = 0; mt < 4; ++mt) {
        int row = wm * 64 + mt * 16 + rA;
        relA[mt] = (uint32_t)(row * 64) + ((uint32_t)((((row >> 1) & 3) ^ csel)) << 4);
    }
    {
        int row = wn * 32 + rA;
        relB0 = 8192u + (uint32_t)(row * 64) + ((uint32_t)((((row >> 1) & 3) ^ csel)) << 4);
        row += 16;
        relB1 = 8192u + (uint32_t)(row * 64) + ((uint32_t)((((row >> 1) & 3) ^ csel)) << 4);
    }

    float acc[4][4][4];
    #pragma unroll
    for (int i = 0; i < 4; ++i)
        #pragma unroll
        for (int j = 0; j < 4; ++j)
            #pragma unroll
            for (int q = 0; q < 4; ++q) acc[i][j][q] = 0.f;

    #pragma unroll
    for (int s = 0; s < 2; ++s) {
        uint32_t st = sb + s * STAGE_BYTES;
        CPA16(st + dA0, asrc0 + s * 32);
        CPA16(st + dA1, asrc1 + s * 32);
        CPA16(st + 8192 + dA0, bsrc0 + s * 32);
        CPA16(st + 8192 + dA1, bsrc1 + s * 32);
        CPCOMMIT();
    }

    const int NK = ND / 32;   // 32
    int stage = 0;
    for (int kt = 0; kt < NK; ++kt) {
        if (kt < NK - 1) { CPWAIT(1); } else { CPWAIT(0); }
        __syncthreads();
        if (kt + 2 < NK) {
            uint32_t st = sb + ((kt + 2) % 3) * STAGE_BYTES;
            int off = (kt + 2) * 32;
            CPA16(st + dA0, asrc0 + off);
            CPA16(st + dA1, asrc1 + off);
            CPA16(st + 8192 + dA0, bsrc0 + off);
            CPA16(st + 8192 + dA1, bsrc1 + off);
            CPCOMMIT();
        }
        uint32_t As = sb + stage * STAGE_BYTES;
        // hoist B fragments for BOTH ks halves
        uint32_t B0a[4], B1a[4], B0b[4], B1b[4];
        LDM_X4(B0a[0], B0a[1], B0a[2], B0a[3], As + relB0);
        LDM_X4(B1a[0], B1a[1], B1a[2], B1a[3], As + relB1);
        LDM_X4(B0b[0], B0b[1], B0b[2], B0b[3], As + (relB0 ^ 32u));
        LDM_X4(B1b[0], B1b[1], B1b[2], B1b[3], As + (relB1 ^ 32u));
        #pragma unroll
        for (int ks = 0; ks < 2; ++ks) {
            uint32_t kx = (uint32_t)(ks << 5);
            const uint32_t* B0 = ks ? B0b : B0a;
            const uint32_t* B1 = ks ? B1b : B1a;
            uint32_t a[4][4];
            #pragma unroll
            for (int mt = 0; mt < 4; ++mt)
                LDM_X4(a[mt][0], a[mt][1], a[mt][2], a[mt][3], As + (relA[mt] ^ kx));
            #pragma unroll
            for (int mt = 0; mt < 4; ++mt) {
                MMA16(acc[mt][0], a[mt], B0[0], B0[2]);
                MMA16(acc[mt][1], a[mt], B0[1], B0[3]);
                MMA16(acc[mt][2], a[mt], B1[0], B1[2]);
                MMA16(acc[mt][3], a[mt], B1[1], B1[3]);
            }
        }
        stage = stage + 1; if (stage == 3) stage = 0;
    }

    // epilogue: acc[mt][nt] (a-cols) pairs with acc[mt][nt+2] (b-cols), nt in {0,1}.
    #pragma unroll
    for (int mt = 0; mt < 4; ++mt) {
        #pragma unroll
        for (int hf = 0; hf < 2; ++hf) {
            int row = wm * 64 + mt * 16 + grp + hf * 8;
            int rr = m0 + row;
            if (rr < cnt) {
                __half* dst = g_h16 + ((size_t)e * NT + rr) * NH + n0 + wn * 16;
                #pragma unroll
                for (int nt = 0; nt < 2; ++nt) {
                    float a0 = acc[mt][nt][hf * 2 + 0];
                    float a1 = acc[mt][nt][hf * 2 + 1];
                    float b0 = acc[mt][nt + 2][hf * 2 + 0];
                    float b1 = acc[mt][nt + 2][hf * 2 + 1];
                    float h0 = a0 / (1.f + __expf(-a0)) * b0;
                    float h1 = a1 / (1.f + __expf(-a1)) * b1;
                    *(__half2*)(dst + nt * 8 + 2 * tig) = __floats2half2_rn(h0, h1);
                }
            }
        }
    }
}

// =====================================================================
// ffn2: C[128 x 128] = g_h16 rows @ w_out16 rows^T, K = 512.
// Epilogue: gate-scale, scatter rows to g_y[tokslot].
// =====================================================================
__global__ void __launch_bounds__(256, 2)
ffn2_h(void) {
    __shared__ __align__(128) uint8_t smem[3 * STAGE_BYTES];
    int e = blockIdx.z;
    int cnt = g_cnt[e];
    int m0 = blockIdx.y * 128;
    if (m0 >= cnt) return;
    int n0 = blockIdx.x * 128;

    uint32_t sb = smem_u32(smem);
    int t = threadIdx.x;
    int lane = t & 31, wid = t >> 5;
    int wm = wid & 1, wn = wid >> 1;
    int grp = lane >> 2, tig = lane & 3;
    int rA = (lane & 7) + ((lane >> 3) & 1) * 8;
    int csel = lane >> 4;

    int lr = t >> 2;
    int lc = t & 3;
    int r0 = m0 + lr, r1 = r0 + 64;
    int rc0 = r0 < cnt ? r0 : cnt - 1;
    int rc1 = r1 < cnt ? r1 : cnt - 1;
    const __half* asrc0 = g_h16 + ((size_t)e * NT + rc0) * NH + lc * 8;
    const __half* asrc1 = g_h16 + ((size_t)e * NT + rc1) * NH + lc * 8;
    const __half* bsrc0 = g_wout16 + ((size_t)e * ND + n0 + lr) * NH + lc * 8;
    const __half* bsrc1 = g_wout16 + ((size_t)e * ND + n0 + lr + 64) * NH + lc * 8;
    uint32_t swc = (uint32_t)((lc ^ ((lr >> 1) & 3)) << 4);
    uint32_t dA0 = lr * 64 + swc;
    uint32_t dA1 = dA0 + 4096;

    uint32_t relA[4], relB0, relB1;
    #pragma unroll
    for (int mt = 0; mt < 4; ++mt) {
        int row = wm * 64 + mt * 16 + rA;
        relA[mt] = (uint32_t)(row * 64) + ((uint32_t)((((row >> 1) & 3) ^ csel)) << 4);
    }
    {
        int row = wn * 32 + rA;
        relB0 = 8192u + (uint32_t)(row * 64) + ((uint32_t)((((row >> 1) & 3) ^ csel)) << 4);
        row += 16;
        relB1 = 8192u + (uint32_t)(row * 64) + ((uint32_t)((((row >> 1) & 3) ^ csel)) << 4);
    }

    float acc[4][4][4];
    #pragma unroll
    for (int i = 0; i < 4; ++i)
        #pragma unroll
        for (int j = 0; j < 4; ++j)
            #pragma unroll
            for (int q = 0; q < 4; ++q) acc[i][j][q] = 0.f;

    #pragma unroll
    for (int s = 0; s < 2; ++s) {
        uint32_t st = sb + s * STAGE_BYTES;
        CPA16(st + dA0, asrc0 + s * 32);
        CPA16(st + dA1, asrc1 + s * 32);
        CPA16(st + 8192 + dA0, bsrc0 + s * 32);
        CPA16(st + 8192 + dA1, bsrc1 + s * 32);
        CPCOMMIT();
    }

    const int NK = NH / 32;   // 16
    int stage = 0;
    for (int kt = 0; kt < NK; ++kt) {
        if (kt < NK - 1) { CPWAIT(1); } else { CPWAIT(0); }
        __syncthreads();
        if (kt + 2 < NK) {
            uint32_t st = sb + ((kt + 2) % 3) * STAGE_BYTES;
            int off = (kt + 2) * 32;
            CPA16(st + dA0, asrc0 + off);
            CPA16(st + dA1, asrc1 + off);
            CPA16(st + 8192 + dA0, bsrc0 + off);
            CPA16(st + 8192 + dA1, bsrc1 + off);
            CPCOMMIT();
        }
        uint32_t As = sb + stage * STAGE_BYTES;
        uint32_t B0a[4], B1a[4], B0b[4], B1b[4];
        LDM_X4(B0a[0], B0a[1], B0a[2], B0a[3], As + relB0);
        LDM_X4(B1a[0], B1a[1], B1a[2], B1a[3], As + relB1);
        LDM_X4(B0b[0], B0b[1], B0b[2], B0b[3], As + (relB0 ^ 32u));
        LDM_X4(B1b[0], B1b[1], B1b[2], B1b[3], As + (relB1 ^ 32u));
        #pragma unroll
        for (int ks = 0; ks < 2; ++ks) {
            uint32_t kx = (uint32_t)(ks << 5);
            const uint32_t* B0 = ks ? B0b : B0a;
            const uint32_t* B1 = ks ? B1b : B1a;
            uint32_t a[4][4];
            #pragma unroll
            for (int mt = 0; mt < 4; ++mt)
                LDM_X4(a[mt][0], a[mt][1], a[mt][2], a[mt][3], As + (relA[mt] ^ kx));
            #pragma unroll
            for (int mt = 0; mt < 4; ++mt) {
                MMA16(acc[mt][0], a[mt], B0[0], B0[2]);
                MMA16(acc[mt][1], a[mt], B0[1], B0[3]);
                MMA16(acc[mt][2], a[mt], B1[0], B1[2]);
                MMA16(acc[mt][3], a[mt], B1[1], B1[3]);
            }
        }
        stage = stage + 1; if (stage == 3) stage = 0;
    }

    #pragma unroll
    for (int mt = 0; mt < 4; ++mt) {
        #pragma unroll
        for (int hf = 0; hf < 2; ++hf) {
            int row = wm * 64 + mt * 16 + grp + hf * 8;
            int rr = m0 + row;
            if (rr < cnt) {
                int   ts = g_tokslot[e * NT + rr];
                float gt = g_gate[e * NT + rr];
                float* dst = g_y + (size_t)ts * ND + n0;
                #pragma unroll
                for (int nt = 0; nt < 4; ++nt) {
                    int col = wn * 32 + nt * 8 + 2 * tig;
                    float2 v = make_float2(acc[mt][nt][hf * 2 + 0] * gt,
                                           acc[mt][nt][hf * 2 + 1] * gt);
                    *(float2*)(dst + col) = v;
                }
            }
        }
    }
}

// out[t] = y[2t] + y[2t+1]; 2 float4 per thread (MLP=2).
// Also re-zeroes g_cnt for the next graph replay.
__global__ void combine_kernel(float* __restrict__ out) {
    if (blockIdx.x == 0 && threadIdx.x < NE) g_cnt[threadIdx.x] = 0;
    int base = blockIdx.x * blockDim.x + threadIdx.x;
    const int half = NT * ND / 8;   // float4s per pass
    const float4* y4 = reinterpret_cast<const float4*>(g_y);
    #pragma unroll
    for (int u = 0; u < 2; ++u) {
        int i = base + u * half;
        int t = i >> 8, c = i & 255;
        float4 a = y4[(size_t)(2 * t) * 256 + c];
        float4 b = y4[(size_t)(2 * t + 1) * 256 + c];
        reinterpret_cast<float4*>(out)[i] =
            make_float4(a.x + b.x, a.y + b.y, a.z + b.z, a.w + b.w);
    }
}

extern "C" void kernel_launch(void* const* d_in, const int* in_sizes, int n_in,
                              void* d_out, int out_size) {
    const float* x     = (const float*)d_in[0];
    const float* wr    = (const float*)d_in[1];
    const float* w_in  = (const float*)d_in[2];
    const float* w_out = (const float*)d_in[3];
    float* out = (float*)d_out;

    float* logits;
    if (out_size >= NT * ND + NT * NE) {
        logits = out + (size_t)NT * ND;
    } else {
        cudaGetSymbolAddress((void**)&logits, g_logits_scratch);
    }

    __half *px16, *pwin16, *pwout16;
    cudaGetSymbolAddress((void**)&px16, g_x16);
    cudaGetSymbolAddress((void**)&pwin16, g_win16);
    cudaGetSymbolAddress((void**)&pwout16, g_wout16);

    prep_kernel<<<NT + CVT_BLOCKS, 256>>>(x, wr, logits, px16,
                                          w_in, pwin16, w_out, pwout16);
    ffn1_h<<<dim3(NH / 64, NT / 128, NE), 256>>>();
    ffn2_h<<<dim3(ND / 128, NT / 128, NE), 256>>>();
    combine_kernel<<<(NT * ND / 8 + 255) / 256, 256>>>(out);
}